// round 13
// baseline (speedup 1.0000x reference)
#include <cuda_runtime.h>

#define Nn      1000
#define NP      1024
#define Bb      8
#define GRID    250
#define NTHREAD 512

// Scratch (static __device__ — no allocation). Padded to NP.
__device__ float4 g_EA[NP];
__device__ float4 g_EB[NP];       // pad rows = (0,0,0,1) -> d contribution 1, w = 0
__device__ float4 g_xt[2 * NP];   // xt[i] = x[0..7][i] transposed; pad rows = 0
__device__ float  g_cc[32];       // c0/c1/c2 [k][m] (18) + Wf2v (3) + bf2v (1)
__device__ unsigned long long g_bar = 0ULL;   // monotonic ticket counter (never reset)

// ---- packed f32x2 helper (Blackwell) ----
__device__ __forceinline__ void ffma2(float2& d, const float2 a, const float2 b) {
    asm("fma.rn.f32x2 %0, %1, %2, %0;"
        : "+l"(reinterpret_cast<unsigned long long&>(d))
        : "l"(reinterpret_cast<const unsigned long long&>(a)),
          "l"(reinterpret_cast<const unsigned long long&>(b)));
}

// ---------------------------------------------------------------------------
// Single persistent kernel: 250 blocks x 512 threads, 2 blocks/SM (all
// co-resident: 250 <= 148*2). Phase 1: each block preps its own 4 rows +
// redundant global X + coeffs. Grid ticket barrier. Phase 2: 4 warps per
// row, j-quarter split (8 pairs/lane, all 8 batches, no duplicated work).
// ---------------------------------------------------------------------------
__global__ void __launch_bounds__(NTHREAD, 2) k_all(
    const float* __restrict__ x,
    const float* __restrict__ W1,   const float* __restrict__ b1,
    const float* __restrict__ W2,   const float* __restrict__ b2,
    const float* __restrict__ Wf1e, const float* __restrict__ bf1e,
    const float* __restrict__ Wf2e, const float* __restrict__ bf2e,
    const float* __restrict__ Wfk,  const float* __restrict__ bfk,
    const float* __restrict__ Wf1v, const float* __restrict__ bf1v,
    const float* __restrict__ Wf2v, const float* __restrict__ bf2v,
    float* __restrict__ out)
{
    __shared__ float s_w[16];
    __shared__ float s_X;
    __shared__ float s_coef[12];     // aA[3], cA[3], aB[3], cB[3]
    __shared__ float s_v[16][32];    // per-warp reduced slots

    const int tid = threadIdx.x;
    const int bid = blockIdx.x;

    // ===================== Phase 1 (all blocks work) ========================
    const int myrow = bid * 4 + tid;          // valid for tid < 4 (max 999)
    float sxi = 0.f;
    if (tid < 4) {
        float vr[8];
        #pragma unroll
        for (int b = 0; b < 8; b++) {
            vr[b] = x[b * Nn + myrow];
            sxi += vr[b];
        }
        g_xt[2 * myrow]     = make_float4(vr[0], vr[1], vr[2], vr[3]);
        g_xt[2 * myrow + 1] = make_float4(vr[4], vr[5], vr[6], vr[7]);
    } else if (bid == GRID - 1 && tid < 28) {
        // pad rows 1000..1023 (24 rows) written by last block, threads 4..27
        const int p = Nn + (tid - 4);
        g_xt[2 * p]     = make_float4(0.f, 0.f, 0.f, 0.f);
        g_xt[2 * p + 1] = make_float4(0.f, 0.f, 0.f, 0.f);
        g_EA[p] = make_float4(0.f, 0.f, 0.f, 0.f);
        g_EB[p] = make_float4(0.f, 0.f, 0.f, 1.f);   // d += 1, w = 0
    }

    // redundant global X: contiguous x as 2000 float4 (L2-shared)
    {
        const float4* x4 = (const float4*)x;
        float xs = 0.f;
        #pragma unroll 1
        for (int t = tid; t < 2000; t += NTHREAD) {
            float4 a = x4[t];
            xs += (a.x + a.y) + (a.z + a.w);
        }
        #pragma unroll
        for (int off = 16; off > 0; off >>= 1)
            xs += __shfl_xor_sync(0xffffffffu, xs, off);
        if ((tid & 31) == 0) s_w[tid >> 5] = xs;
    }
    __syncthreads();
    if (tid == 0) {
        float s = 0.f;
        #pragma unroll
        for (int w = 0; w < 16; w++) s += s_w[w];    // fixed order
        s_X = s;
    }
    __syncthreads();
    const float X = s_X;

    // coefficients (warp 0, redundant across lanes)
    if (tid < 32) {
        float alpha[2], beta[2], gamma[2];
        #pragma unroll
        for (int f = 0; f < 2; f++) {
            float sa = 0.f, sb = 0.f, sg = 0.f;
            #pragma unroll
            for (int e = 0; e < 4; e++) {
                float we = Wf1e[(2 * e) * 2 + f];
                float wo = Wf1e[(2 * e + 1) * 2 + f];
                sa += W1[e] * we;
                sb += W1[e] * wo;
                sg += b1[e] * (we + wo);
            }
            alpha[f] = (float)Nn * sa;
            beta[f]  = sb;
            gamma[f] = (float)Nn * (sg + bf1e[f]);
        }
        float ap[3], cv[3];
        #pragma unroll
        for (int vv = 0; vv < 3; vv++) {
            float a = 0.f, bq = 0.f, gg = 0.f;
            #pragma unroll
            for (int f = 0; f < 2; f++) {
                float w = Wf1v[f * 3 + vv];
                a  += alpha[f] * w;
                bq += beta[f]  * w;
                gg += gamma[f] * w;
            }
            gg += bf1v[vv];
            ap[vv] = a;
            cv[vv] = bq * X + (float)Bb * gg;
        }
        #pragma unroll
        for (int k = 0; k < 3; k++) {
            float s1 = 0.f, s2 = 0.f, s3 = 0.f, s4 = 0.f;
            #pragma unroll
            for (int vv = 0; vv < 3; vv++) {
                float we = Wf2e[(2 * vv) * 3 + k];
                float wo = Wf2e[(2 * vv + 1) * 3 + k];
                s1 += ap[vv] * we;  s2 += cv[vv] * we;
                s3 += ap[vv] * wo;  s4 += cv[vv] * wo;
            }
            if (tid == 0) {
                s_coef[k]     = s1;            // aA
                s_coef[3 + k] = s2 + bf2e[k];  // cA
                s_coef[6 + k] = s3;            // aB
                s_coef[9 + k] = s4;            // cB
            }
        }
        if (bid == 0 && tid == 0) {
            #pragma unroll
            for (int k = 0; k < 3; k++)
                #pragma unroll
                for (int m = 0; m < 2; m++) {
                    float u1 = 0.f, v1 = 0.f, u2 = 0.f, v2 = 0.f;
                    #pragma unroll
                    for (int e = 0; e < 4; e++) {
                        float we = Wfk[k * 16 + (2 * e) * 2 + m];
                        float wo = Wfk[k * 16 + (2 * e + 1) * 2 + m];
                        u1 += W2[e] * we;  v1 += b2[e] * we;
                        u2 += W2[e] * wo;  v2 += b2[e] * wo;
                    }
                    int km = k * 2 + m;
                    g_cc[km * 3 + 0] = v1 + v2 + bfk[km];
                    g_cc[km * 3 + 1] = u1;
                    g_cc[km * 3 + 2] = u2;
                }
            g_cc[18] = Wf2v[0]; g_cc[19] = Wf2v[1];
            g_cc[20] = Wf2v[2]; g_cc[21] = bf2v[0];
        }
    }
    __syncthreads();

    // EA/EB for my 4 rows (per-side max-subtracted; exact for softmax)
    if (tid < 4) {
        float A0 = fmaf(s_coef[0], sxi, s_coef[3]);
        float A1 = fmaf(s_coef[1], sxi, s_coef[4]);
        float A2 = fmaf(s_coef[2], sxi, s_coef[5]);
        float mA = fmaxf(A0, fmaxf(A1, A2));
        g_EA[myrow] = make_float4(__expf(A0 - mA), __expf(A1 - mA), __expf(A2 - mA), 0.f);
        float B0 = fmaf(s_coef[6], sxi, s_coef[9]);
        float B1 = fmaf(s_coef[7], sxi, s_coef[10]);
        float B2 = fmaf(s_coef[8], sxi, s_coef[11]);
        float mB = fmaxf(B0, fmaxf(B1, B2));
        g_EB[myrow] = make_float4(__expf(B0 - mB), __expf(B1 - mB), __expf(B2 - mB), 0.f);
    }

    // ================= grid-wide ticket barrier (replay-safe) ===============
    __syncthreads();
    __threadfence();                        // release
    if (tid == 0) {
        unsigned long long ticket = atomicAdd(&g_bar, 1ULL);
        unsigned long long target = ticket - (ticket % GRID) + GRID;
        while (*(volatile unsigned long long*)&g_bar < target) { }
    }
    __syncthreads();
    __threadfence();                        // acquire

    // ============ Phase 2: 4 warps per row, j-quarter split =================
    const int lane = tid & 31;
    const int warp = tid >> 5;              // 0..15
    const int r    = warp >> 2;             // row within block: 0..3
    const int qu   = warp & 3;              // j-quarter: [qu*256, qu*256+256)
    const int i    = bid * 4 + r;           // 0..999 exactly
    const float4 ea = g_EA[i];
    const float eav[3] = {ea.x, ea.y, ea.z};

    // folded coefficients q[m][k] = c2[k,m] * ea_k
    float q0[3], q1[3];
    #pragma unroll
    for (int k = 0; k < 3; k++) {
        q0[k] = g_cc[(k * 2 + 0) * 3 + 2] * eav[k];
        q1[k] = g_cc[(k * 2 + 1) * 3 + 2] * eav[k];
    }

    float t0 = 0.f, t1 = 0.f, t2 = 0.f;
    float2 a0[4], a1[4];                    // V0/V1 pairs (b=2bp, 2bp+1)
    #pragma unroll
    for (int bp = 0; bp < 4; bp++) {
        a0[bp] = make_float2(0.f, 0.f);
        a1[bp] = make_float2(0.f, 0.f);
    }

    #pragma unroll 1
    for (int u = 0; u < 2; u++) {
        const int jbase = qu * 256 + u * 128 + lane;
        // stage 1: 4 eb vectors, d into .w (pad rows: d=1, w=0, x=0 -> 0 contrib)
        float4 eb[4];
        #pragma unroll
        for (int t = 0; t < 4; t++) eb[t] = g_EB[jbase + t * 32];
        #pragma unroll
        for (int t = 0; t < 4; t++)
            eb[t].w = fmaf(ea.x, eb[t].x, fmaf(ea.y, eb[t].y, fmaf(ea.z, eb[t].z, eb[t].w)));
        // Montgomery-4: d in (1,4] -> product <= 256, safe
        float p1 = eb[0].w * eb[1].w;
        float p2 = p1 * eb[2].w;
        float p3 = p2 * eb[3].w;
        float rr = __fdividef(1.f, p3);
        float inv[4];
        inv[3]   = rr * p2;
        float r2 = rr * eb[3].w;
        inv[2]   = r2 * p1;
        float r1 = r2 * eb[2].w;
        inv[1]   = r1 * eb[0].w;
        inv[0]   = r1 * eb[1].w;

        // stage 2: stream x per pair (keeps live regs low)
        #pragma unroll
        for (int t = 0; t < 4; t++) {
            const int j = jbase + t * 32;
            float4 xa = g_xt[2 * j];
            float4 xb = g_xt[2 * j + 1];
            float w0 = eb[t].x * inv[t];
            float w1 = eb[t].y * inv[t];
            float w2 = eb[t].z * inv[t];
            t0 += w0; t1 += w1; t2 += w2;
            float s0 = fmaf(q0[0], w0, fmaf(q0[1], w1, q0[2] * w2));
            float s1 = fmaf(q1[0], w0, fmaf(q1[1], w1, q1[2] * w2));
            float2 sp0 = make_float2(s0, s0);
            float2 sp1 = make_float2(s1, s1);
            ffma2(a0[0], sp0, make_float2(xa.x, xa.y));
            ffma2(a0[1], sp0, make_float2(xa.z, xa.w));
            ffma2(a0[2], sp0, make_float2(xb.x, xb.y));
            ffma2(a0[3], sp0, make_float2(xb.z, xb.w));
            ffma2(a1[0], sp1, make_float2(xa.x, xa.y));
            ffma2(a1[1], sp1, make_float2(xa.z, xa.w));
            ffma2(a1[2], sp1, make_float2(xb.x, xb.y));
            ffma2(a1[3], sp1, make_float2(xb.z, xb.w));
        }
    }

    // 19 values -> 32 slots; distributed exchange reduce within warp
    float vv[32];
    vv[0] = t0; vv[1] = t1; vv[2] = t2;
    #pragma unroll
    for (int bp = 0; bp < 4; bp++) {
        vv[3 + 2 * bp]      = a0[bp].x;  vv[3 + 2 * bp + 1]  = a0[bp].y;
        vv[11 + 2 * bp]     = a1[bp].x;  vv[11 + 2 * bp + 1] = a1[bp].y;
    }
    #pragma unroll
    for (int s = 19; s < 32; s++) vv[s] = 0.f;

    #pragma unroll
    for (int lev = 0; lev < 5; lev++) {
        const int dd = 1 << lev;
        const int half = 16 >> lev;
        const bool up = (lane & dd) != 0;
        #pragma unroll
        for (int s = 0; s < half; s++) {
            float keep = up ? vv[s + half] : vv[s];
            float send = up ? vv[s] : vv[s + half];
            float recv = __shfl_xor_sync(0xffffffffu, send, dd);
            vv[s] = keep + recv;
        }
    }
    // lane l holds total of slot bitrev5(l) -> canonical slot index in smem
    const int br = ((lane & 1) << 4) | ((lane & 2) << 2) | (lane & 4)
                 | ((lane & 8) >> 2) | ((lane & 16) >> 4);
    s_v[warp][br] = vv[0];
    __syncthreads();

    // warp 4r, lanes 0..7 finish row i: combine the 4 j-quarter warps
    if ((warp & 3) == 0 && lane < 8) {
        const int b = lane;
        float xbi = ((const float*)&g_xt[2 * i])[b];
        float T0 = (s_v[warp][0] + s_v[warp + 1][0]) + (s_v[warp + 2][0] + s_v[warp + 3][0]);
        float T1 = (s_v[warp][1] + s_v[warp + 1][1]) + (s_v[warp + 2][1] + s_v[warp + 3][1]);
        float T2 = (s_v[warp][2] + s_v[warp + 1][2]) + (s_v[warp + 2][2] + s_v[warp + 3][2]);
        float V0 = (s_v[warp][3 + b] + s_v[warp + 1][3 + b])
                 + (s_v[warp + 2][3 + b] + s_v[warp + 3][3 + b]);
        float V1 = (s_v[warp][11 + b] + s_v[warp + 1][11 + b])
                 + (s_v[warp + 2][11 + b] + s_v[warp + 3][11 + b]);
        float eaT[3] = {eav[0] * T0, eav[1] * T1, eav[2] * T2};
        float ve0 = V0, ve1 = V1;
        #pragma unroll
        for (int k = 0; k < 3; k++) {
            ve0 += fmaf(xbi, g_cc[(k * 2 + 0) * 3 + 1], g_cc[(k * 2 + 0) * 3 + 0]) * eaT[k];
            ve1 += fmaf(xbi, g_cc[(k * 2 + 1) * 3 + 1], g_cc[(k * 2 + 1) * 3 + 0]) * eaT[k];
        }
        out[b * Nn + i] = xbi * (1.f + g_cc[20]) + g_cc[21]
                        + ve0 * g_cc[18] + ve1 * g_cc[19];
    }
}

extern "C" void kernel_launch(void* const* d_in, const int* in_sizes, int n_in,
                              void* d_out, int out_size)
{
    (void)in_sizes; (void)n_in; (void)out_size;
    k_all<<<GRID, NTHREAD>>>(
        (const float*)d_in[0],
        (const float*)d_in[1],  (const float*)d_in[2],
        (const float*)d_in[3],  (const float*)d_in[4],
        (const float*)d_in[5],  (const float*)d_in[6],
        (const float*)d_in[7],  (const float*)d_in[8],
        (const float*)d_in[9],  (const float*)d_in[10],
        (const float*)d_in[11], (const float*)d_in[12],
        (const float*)d_in[13], (const float*)d_in[14],
        (float*)d_out);
}

// round 15
// speedup vs baseline: 1.1805x; 1.1805x over previous
#include <cuda_runtime.h>

#define Nn      1000
#define NP      1024
#define Bb      8
#define GRID    125
#define NTHREAD 512

// Scratch (static __device__ — no allocation). Padded to NP.
__device__ float4 g_EA[NP];
__device__ float4 g_EB[NP];       // pad rows = (0,0,0,1) -> d contribution 1, w = 0
__device__ float4 g_xt[2 * NP];   // xt[i] = x[0..7][i] transposed; pad rows = 0
__device__ unsigned long long g_bar = 0ULL;   // monotonic ticket counter (never reset)

// ---- packed f32x2 helper (Blackwell) ----
__device__ __forceinline__ void ffma2(float2& d, const float2 a, const float2 b) {
    asm("fma.rn.f32x2 %0, %1, %2, %0;"
        : "+l"(reinterpret_cast<unsigned long long&>(d))
        : "l"(reinterpret_cast<const unsigned long long&>(a)),
          "l"(reinterpret_cast<const unsigned long long&>(b)));
}

// ---------------------------------------------------------------------------
// Single persistent kernel: 125 blocks x 512 threads (R9 structure).
// Phase 1 (latency-overlapped): tid<8 loads its 8 rows; ALL threads stream x
// for the global sum X; warp 1 concurrently loads all weights (one MLP'd
// miss) and computes X-FREE coefficient parts (cA = cAx*X + cA0) plus the
// combine constants into block-local smem. ONE syncthreads; tid<8 folds X
// in and writes EA/EB. Grid ticket barrier. Phase 2: R9 verbatim (2 warps
// per row, 16 pairs/lane, Montgomery-4), cc constants read from smem.
// ---------------------------------------------------------------------------
__global__ void __launch_bounds__(NTHREAD, 1) k_all(
    const float* __restrict__ x,
    const float* __restrict__ W1,   const float* __restrict__ b1,
    const float* __restrict__ W2,   const float* __restrict__ b2,
    const float* __restrict__ Wf1e, const float* __restrict__ bf1e,
    const float* __restrict__ Wf2e, const float* __restrict__ bf2e,
    const float* __restrict__ Wfk,  const float* __restrict__ bfk,
    const float* __restrict__ Wf1v, const float* __restrict__ bf1v,
    const float* __restrict__ Wf2v, const float* __restrict__ bf2v,
    float* __restrict__ out)
{
    __shared__ float s_w[16];
    __shared__ float s_cf[18];       // aA[3], cAx[3], cA0[3], aB[3], cBx[3], cB0[3]
    __shared__ float s_cc[24];       // c0/c1/c2 [k][m] (18) + Wf2v (3) + bf2v (1)
    __shared__ float s_v[16][32];    // per-warp reduced slots

    const int tid = threadIdx.x;
    const int bid = blockIdx.x;

    // ===================== Phase 1 (overlapped) =============================
    // (A) my 8 rows: transpose + row-sum (issue these strided loads first)
    const int myrow = bid * 8 + tid;          // valid for tid < 8
    float sxi = 0.f;
    if (tid < 8) {
        float vr[8];
        #pragma unroll
        for (int b = 0; b < 8; b++) {
            vr[b] = x[b * Nn + myrow];
            sxi += vr[b];
        }
        g_xt[2 * myrow]     = make_float4(vr[0], vr[1], vr[2], vr[3]);
        g_xt[2 * myrow + 1] = make_float4(vr[4], vr[5], vr[6], vr[7]);
    } else if (bid == GRID - 1 && tid >= 8 && tid < 32) {
        // pad rows 1000..1023 (24 rows)
        const int p = Nn + (tid - 8);
        g_xt[2 * p]     = make_float4(0.f, 0.f, 0.f, 0.f);
        g_xt[2 * p + 1] = make_float4(0.f, 0.f, 0.f, 0.f);
        g_EA[p] = make_float4(0.f, 0.f, 0.f, 0.f);
        g_EB[p] = make_float4(0.f, 0.f, 0.f, 1.f);   // d += 1, w = 0
    }

    // (B) warp 1: weights -> X-free coefficient parts + combine constants.
    //     All loads are independent -> single MLP-overlapped cold miss.
    if (tid >= 32 && tid < 64) {
        // ---- load all weights into registers (redundant per lane) ----
        // Wf1e shape: (2*EMB, F1E) = (8, 2) -> 16 floats
        float w1[4], bb1[4], wf1e[16], bv1e[2], wf1v[6], bv1v[3], wf2e[18], bv2e[3];
        #pragma unroll
        for (int e = 0; e < 4; e++) { w1[e] = W1[e]; bb1[e] = b1[e]; }
        #pragma unroll
        for (int q = 0; q < 16; q++) wf1e[q] = Wf1e[q];
        bv1e[0] = bf1e[0]; bv1e[1] = bf1e[1];
        #pragma unroll
        for (int q = 0; q < 6; q++) wf1v[q] = Wf1v[q];
        bv1v[0] = bf1v[0]; bv1v[1] = bf1v[1]; bv1v[2] = bf1v[2];
        #pragma unroll
        for (int q = 0; q < 18; q++) wf2e[q] = Wf2e[q];
        bv2e[0] = bf2e[0]; bv2e[1] = bf2e[1]; bv2e[2] = bf2e[2];

        // ---- X-free coefficient chain ----
        float alpha[2], beta[2], gamma[2];
        #pragma unroll
        for (int f = 0; f < 2; f++) {
            float sa = 0.f, sb = 0.f, sg = 0.f;
            #pragma unroll
            for (int e = 0; e < 4; e++) {
                float we = wf1e[(2 * e) * 2 + f];
                float wo = wf1e[(2 * e + 1) * 2 + f];
                sa += w1[e] * we;
                sb += w1[e] * wo;
                sg += bb1[e] * (we + wo);
            }
            alpha[f] = (float)Nn * sa;
            beta[f]  = sb;
            gamma[f] = (float)Nn * (sg + bv1e[f]);
        }
        float ap[3], bq[3], gg[3];
        #pragma unroll
        for (int vv = 0; vv < 3; vv++) {
            float a = 0.f, bqv = 0.f, ggv = 0.f;
            #pragma unroll
            for (int f = 0; f < 2; f++) {
                float w = wf1v[f * 3 + vv];
                a   += alpha[f] * w;
                bqv += beta[f]  * w;
                ggv += gamma[f] * w;
            }
            ap[vv] = a;
            bq[vv] = bqv;
            gg[vv] = ggv + bv1v[vv];
        }
        if (tid == 32) {
            #pragma unroll
            for (int k = 0; k < 3; k++) {
                float sA = 0.f, sAx = 0.f, sA0 = 0.f;
                float sB = 0.f, sBx = 0.f, sB0 = 0.f;
                #pragma unroll
                for (int vv = 0; vv < 3; vv++) {
                    float we = wf2e[(2 * vv) * 3 + k];
                    float wo = wf2e[(2 * vv + 1) * 3 + k];
                    sA  += ap[vv] * we;  sAx += bq[vv] * we;  sA0 += gg[vv] * we;
                    sB  += ap[vv] * wo;  sBx += bq[vv] * wo;  sB0 += gg[vv] * wo;
                }
                s_cf[k]      = sA;                          // aA
                s_cf[3 + k]  = sAx;                         // cAx
                s_cf[6 + k]  = (float)Bb * sA0 + bv2e[k];   // cA0 (+bias)
                s_cf[9 + k]  = sB;                          // aB
                s_cf[12 + k] = sBx;                         // cBx
                s_cf[15 + k] = (float)Bb * sB0;             // cB0
            }
            // combine constants (X-free), block-local
            #pragma unroll
            for (int k = 0; k < 3; k++)
                #pragma unroll
                for (int m = 0; m < 2; m++) {
                    float u1 = 0.f, v1 = 0.f, u2 = 0.f, v2 = 0.f;
                    #pragma unroll
                    for (int e = 0; e < 4; e++) {
                        float we = Wfk[k * 16 + (2 * e) * 2 + m];
                        float wo = Wfk[k * 16 + (2 * e + 1) * 2 + m];
                        u1 += W2[e] * we;  v1 += b2[e] * we;
                        u2 += W2[e] * wo;  v2 += b2[e] * wo;
                    }
                    int km = k * 2 + m;
                    s_cc[km * 3 + 0] = v1 + v2 + bfk[km];
                    s_cc[km * 3 + 1] = u1;
                    s_cc[km * 3 + 2] = u2;
                }
            s_cc[18] = Wf2v[0]; s_cc[19] = Wf2v[1];
            s_cc[20] = Wf2v[2]; s_cc[21] = bf2v[0];
        }
    }

    // (C) all threads: global-X partials (contiguous x as 2000 float4)
    {
        const float4* x4 = (const float4*)x;
        float xs = 0.f;
        #pragma unroll 1
        for (int t = tid; t < 2000; t += NTHREAD) {
            float4 a = x4[t];
            xs += (a.x + a.y) + (a.z + a.w);
        }
        #pragma unroll
        for (int off = 16; off > 0; off >>= 1)
            xs += __shfl_xor_sync(0xffffffffu, xs, off);
        if ((tid & 31) == 0) s_w[tid >> 5] = xs;
    }
    __syncthreads();    // single block-level sync: s_w, s_cf, s_cc all ready

    // (D) tid<8: fold X in, compute EA/EB (per-side max-subtracted; exact)
    if (tid < 8) {
        float X = 0.f;
        #pragma unroll
        for (int w = 0; w < 16; w++) X += s_w[w];    // fixed order
        float A0 = fmaf(s_cf[0], sxi, fmaf(s_cf[3], X, s_cf[6]));
        float A1 = fmaf(s_cf[1], sxi, fmaf(s_cf[4], X, s_cf[7]));
        float A2 = fmaf(s_cf[2], sxi, fmaf(s_cf[5], X, s_cf[8]));
        float mA = fmaxf(A0, fmaxf(A1, A2));
        g_EA[myrow] = make_float4(__expf(A0 - mA), __expf(A1 - mA), __expf(A2 - mA), 0.f);
        float B0 = fmaf(s_cf[9],  sxi, fmaf(s_cf[12], X, s_cf[15]));
        float B1 = fmaf(s_cf[10], sxi, fmaf(s_cf[13], X, s_cf[16]));
        float B2 = fmaf(s_cf[11], sxi, fmaf(s_cf[14], X, s_cf[17]));
        float mB = fmaxf(B0, fmaxf(B1, B2));
        g_EB[myrow] = make_float4(__expf(B0 - mB), __expf(B1 - mB), __expf(B2 - mB), 0.f);
    }

    // ================= grid-wide ticket barrier (replay-safe) ===============
    __syncthreads();
    __threadfence();                        // release
    if (tid == 0) {
        unsigned long long ticket = atomicAdd(&g_bar, 1ULL);
        unsigned long long target = ticket - (ticket % GRID) + GRID;
        while (*(volatile unsigned long long*)&g_bar < target) { }
    }
    __syncthreads();
    __threadfence();                        // acquire

    // ===================== Phase 2: R9 verbatim =============================
    const int lane = tid & 31;
    const int warp = tid >> 5;              // 0..15
    const int r    = warp >> 1;             // 0..7
    const int h    = warp & 1;              // half: j in [h*512, h*512+512)
    const int i    = bid * 8 + r;           // 0..999
    const float4 ea = g_EA[i];
    const float eav[3] = {ea.x, ea.y, ea.z};

    // folded coefficients q[m][k] = c2[k,m] * ea_k  (from smem now)
    float q0[3], q1[3];
    #pragma unroll
    for (int k = 0; k < 3; k++) {
        q0[k] = s_cc[(k * 2 + 0) * 3 + 2] * eav[k];
        q1[k] = s_cc[(k * 2 + 1) * 3 + 2] * eav[k];
    }

    float t0 = 0.f, t1 = 0.f, t2 = 0.f;
    float2 a0[4], a1[4];
    #pragma unroll
    for (int bp = 0; bp < 4; bp++) {
        a0[bp] = make_float2(0.f, 0.f);
        a1[bp] = make_float2(0.f, 0.f);
    }

    #pragma unroll 1
    for (int u = 0; u < 4; u++) {
        float4 eb[4], xa[4], xb[4];
        #pragma unroll
        for (int t = 0; t < 4; t++) {
            const int j = h * 512 + (u * 4 + t) * 32 + lane;
            eb[t] = g_EB[j];
            xa[t] = g_xt[2 * j];
            xb[t] = g_xt[2 * j + 1];
        }
        float d[4];
        #pragma unroll
        for (int t = 0; t < 4; t++)
            d[t] = fmaf(ea.x, eb[t].x, fmaf(ea.y, eb[t].y, fmaf(ea.z, eb[t].z, eb[t].w)));
        // Montgomery batch inversion: 1 MUFU per 4 pairs; d in (1,4] -> safe
        float p1 = d[0] * d[1];
        float p2 = p1 * d[2];
        float p3 = p2 * d[3];
        float rr = __fdividef(1.f, p3);
        float inv[4];
        inv[3]   = rr * p2;
        float r2 = rr * d[3];
        inv[2]   = r2 * p1;
        float r1 = r2 * d[2];
        inv[1]   = r1 * d[0];
        inv[0]   = r1 * d[1];

        #pragma unroll
        for (int t = 0; t < 4; t++) {
            float w0 = eb[t].x * inv[t];
            float w1 = eb[t].y * inv[t];
            float w2 = eb[t].z * inv[t];
            t0 += w0; t1 += w1; t2 += w2;
            float s0 = fmaf(q0[0], w0, fmaf(q0[1], w1, q0[2] * w2));
            float s1 = fmaf(q1[0], w0, fmaf(q1[1], w1, q1[2] * w2));
            float2 xp[4] = { make_float2(xa[t].x, xa[t].y), make_float2(xa[t].z, xa[t].w),
                             make_float2(xb[t].x, xb[t].y), make_float2(xb[t].z, xb[t].w) };
            float2 sp0 = make_float2(s0, s0);
            float2 sp1 = make_float2(s1, s1);
            #pragma unroll
            for (int bp = 0; bp < 4; bp++) {
                ffma2(a0[bp], sp0, xp[bp]);
                ffma2(a1[bp], sp1, xp[bp]);
            }
        }
    }

    // 19 values -> 32 slots; distributed exchange reduce within warp
    float vv[32];
    vv[0] = t0; vv[1] = t1; vv[2] = t2;
    #pragma unroll
    for (int bp = 0; bp < 4; bp++) {
        vv[3 + 2 * bp]      = a0[bp].x;  vv[3 + 2 * bp + 1]  = a0[bp].y;
        vv[11 + 2 * bp]     = a1[bp].x;  vv[11 + 2 * bp + 1] = a1[bp].y;
    }
    #pragma unroll
    for (int s = 19; s < 32; s++) vv[s] = 0.f;

    #pragma unroll
    for (int lev = 0; lev < 5; lev++) {
        const int dd = 1 << lev;
        const int half = 16 >> lev;
        const bool up = (lane & dd) != 0;
        #pragma unroll
        for (int s = 0; s < half; s++) {
            float keep = up ? vv[s + half] : vv[s];
            float send = up ? vv[s] : vv[s + half];
            float recv = __shfl_xor_sync(0xffffffffu, send, dd);
            vv[s] = keep + recv;
        }
    }
    const int br = ((lane & 1) << 4) | ((lane & 2) << 2) | (lane & 4)
                 | ((lane & 8) >> 2) | ((lane & 16) >> 4);
    s_v[warp][br] = vv[0];
    __syncthreads();

    // even warp of each pair finishes the row: lanes 0..7 -> 8 batch outputs
    if (h == 0 && lane < 8) {
        const int b = lane;
        const int w0i = 2 * r, w1i = 2 * r + 1;
        float xbi = ((const float*)&g_xt[2 * i])[b];
        float T0 = s_v[w0i][0] + s_v[w1i][0];
        float T1 = s_v[w0i][1] + s_v[w1i][1];
        float T2 = s_v[w0i][2] + s_v[w1i][2];
        float V0 = s_v[w0i][3 + b]  + s_v[w1i][3 + b];
        float V1 = s_v[w0i][11 + b] + s_v[w1i][11 + b];
        float eaT[3] = {eav[0] * T0, eav[1] * T1, eav[2] * T2};
        float ve0 = V0, ve1 = V1;
        #pragma unroll
        for (int k = 0; k < 3; k++) {
            ve0 += fmaf(xbi, s_cc[(k * 2 + 0) * 3 + 1], s_cc[(k * 2 + 0) * 3 + 0]) * eaT[k];
            ve1 += fmaf(xbi, s_cc[(k * 2 + 1) * 3 + 1], s_cc[(k * 2 + 1) * 3 + 0]) * eaT[k];
        }
        out[b * Nn + i] = xbi * (1.f + s_cc[20]) + s_cc[21]
                        + ve0 * s_cc[18] + ve1 * s_cc[19];
    }
}

extern "C" void kernel_launch(void* const* d_in, const int* in_sizes, int n_in,
                              void* d_out, int out_size)
{
    (void)in_sizes; (void)n_in; (void)out_size;
    k_all<<<GRID, NTHREAD>>>(
        (const float*)d_in[0],
        (const float*)d_in[1],  (const float*)d_in[2],
        (const float*)d_in[3],  (const float*)d_in[4],
        (const float*)d_in[5],  (const float*)d_in[6],
        (const float*)d_in[7],  (const float*)d_in[8],
        (const float*)d_in[9],  (const float*)d_in[10],
        (const float*)d_in[11], (const float*)d_in[12],
        (const float*)d_in[13], (const float*)d_in[14],
        (float*)d_out);
}